// round 15
// baseline (speedup 1.0000x reference)
#include <cuda_runtime.h>
#include <cuda_bf16.h>
#include <stdint.h>

// ApplyRotary: T=32768 tokens, H=32 heads, D=128, ROPE_DIM=64.
// out[t,h,d<32]    =  x[d]*cos[d] - x[d+32]*sin[d]
// out[t,h,32<=d<64]=  x[d]*cos[d] + x[d-32]*sin[d]
// out[t,h,d>=64]   =  x[d]
//
// One WARP per TOKEN, 256-bit ld/st, L2::evict_first on both streams,
// 3-stage pipeline with 2 KB chunks, prime-first prologue + ballot
// segment search (R9 base — best measured, 152.0 us kernel).
// R10 delta: 128-thread CTAs (4 warps), grid 8192, bounds(128,4) —
// same warps/SM and regs, but halved per-CTA prologue bursts into the
// L1tex queue and 2x finer CLC scheduling granularity.

#define N_TOK   32768
#define N_HEAD  32
#define ROPE    64

__device__ __forceinline__ void ldg256_ef(const float* p, float r[8]) {
    asm volatile("ld.global.nc.L2::evict_first.v8.f32 {%0,%1,%2,%3,%4,%5,%6,%7}, [%8];"
        : "=f"(r[0]), "=f"(r[1]), "=f"(r[2]), "=f"(r[3]),
          "=f"(r[4]), "=f"(r[5]), "=f"(r[6]), "=f"(r[7])
        : "l"(p));
}

__device__ __forceinline__ void ldg256(const float* p, float r[8]) {
    asm volatile("ld.global.nc.v8.f32 {%0,%1,%2,%3,%4,%5,%6,%7}, [%8];"
        : "=f"(r[0]), "=f"(r[1]), "=f"(r[2]), "=f"(r[3]),
          "=f"(r[4]), "=f"(r[5]), "=f"(r[6]), "=f"(r[7])
        : "l"(p));
}

__device__ __forceinline__ void stg256_ef(float* p, const float r[8]) {
    asm volatile("st.global.L2::evict_first.v8.f32 [%0], {%1,%2,%3,%4,%5,%6,%7,%8};"
        :: "l"(p),
           "f"(r[0]), "f"(r[1]), "f"(r[2]), "f"(r[3]),
           "f"(r[4]), "f"(r[5]), "f"(r[6]), "f"(r[7])
        : "memory");
}

__global__ __launch_bounds__(128, 4) void rope_kernel(
    const float* __restrict__ in,
    const float* __restrict__ sin_c,
    const float* __restrict__ cos_c,
    const int*   __restrict__ cu,
    float*       __restrict__ out)
{
    const int warp = threadIdx.x >> 5;
    const int lane = threadIdx.x & 31;
    const int t    = blockIdx.x * 4 + warp;   // one token per warp
    const int il   = lane & 15;               // lane within 16-lane head span

    const float* inb  = in  + (size_t)t * (N_HEAD * 128) + 8 * lane;
    float*       outb = out + (size_t)t * (N_HEAD * 128) + 8 * lane;

    // --- Prime the stream pipeline FIRST (independent of the search). ---
    float b[3][2][8];
#pragma unroll
    for (int j = 0; j < 2; j++) ldg256_ef(inb + j * 256,       b[0][j]);
#pragma unroll
    for (int j = 0; j < 2; j++) ldg256_ef(inb + 512 + j * 256, b[1][j]);

    // --- One-shot ballot segment search (resolves under in-flight reads).
    // Lane l holds cu[l] (17 entries); lo = highest lane with cu[lane] <= t.
    const int c_l = (lane <= 16) ? __ldg(cu + lane) : 0x7fffffff;
    const unsigned m = __ballot_sync(0xffffffffu, c_l <= t);
    const int lo = 31 - __clz(m);
    const int off = t - __shfl_sync(0xffffffffu, c_l, lo);

    // sin/cos for this lane's 8 rope dims (reused tables: default policy).
    float s8[8], c8[8];
#pragma unroll
    for (int k = 0; k < 8; k++) { s8[k] = 0.f; c8[k] = 0.f; }
    if (il < 8) {
        ldg256(sin_c + (size_t)off * ROPE + 8 * il, s8);
        ldg256(cos_c + (size_t)off * ROPE + 8 * il, c8);
    }
    const float sg   = (il < 4) ? -1.0f : 1.0f;
    const bool  rope = (il < 8);

    // 8 chunks of 4 heads (2 x 1KB LDG.256 each). 3-stage pipeline:
    // chunks c+1 and c+2 always in flight while chunk c computes/stores.
#pragma unroll
    for (int c = 0; c < 8; c++) {
        const int cur = c % 3;
        const int nxt = (c + 2) % 3;
        if (c < 6) {
#pragma unroll
            for (int j = 0; j < 2; j++)
                ldg256_ef(inb + 512 * (c + 2) + j * 256, b[nxt][j]);
        }

#pragma unroll
        for (int j = 0; j < 2; j++) {
            float r[8];
#pragma unroll
            for (int k = 0; k < 8; k++) {
                const float q = __shfl_xor_sync(0xffffffffu, b[cur][j][k], 4);
                r[k] = rope ? fmaf(sg * q, s8[k], b[cur][j][k] * c8[k]) : b[cur][j][k];
            }
            stg256_ef(outb + 512 * c + j * 256, r);
        }
    }
}

extern "C" void kernel_launch(void* const* d_in, const int* in_sizes, int n_in,
                              void* d_out, int out_size)
{
    const float* in    = (const float*)d_in[0];
    const float* sin_c = (const float*)d_in[1];
    const float* cos_c = (const float*)d_in[2];
    const int*   cu    = (const int*)  d_in[3];
    float*       out   = (float*)d_out;

    const int blocks = N_TOK / 4;   // 8192 blocks, 4 warps each
    rope_kernel<<<blocks, 128>>>(in, sin_c, cos_c, cu, out);
}

// round 16
// speedup vs baseline: 1.0016x; 1.0016x over previous
#include <cuda_runtime.h>
#include <cuda_bf16.h>
#include <stdint.h>

// ApplyRotary: T=32768 tokens, H=32 heads, D=128, ROPE_DIM=64.
// out[t,h,d<32]    =  x[d]*cos[d] - x[d+32]*sin[d]
// out[t,h,32<=d<64]=  x[d]*cos[d] + x[d-32]*sin[d]
// out[t,h,d>=64]   =  x[d]
//
// One WARP per TOKEN, 256-bit ld/st, L2::evict_first on both streams,
// prime-first prologue + ballot segment search (R9 base).
// R11 delta: 4 KB chunks in a 2-stage pipeline — 4x LDG.256 then
// 4x STG.256 per stage. Same 4 KB read lookahead as the 3-stage/2KB
// variant, but HALF the per-warp read<->write burst alternation
// frequency at the memory controller.

#define N_TOK   32768
#define N_HEAD  32
#define ROPE    64

__device__ __forceinline__ void ldg256_ef(const float* p, float r[8]) {
    asm volatile("ld.global.nc.L2::evict_first.v8.f32 {%0,%1,%2,%3,%4,%5,%6,%7}, [%8];"
        : "=f"(r[0]), "=f"(r[1]), "=f"(r[2]), "=f"(r[3]),
          "=f"(r[4]), "=f"(r[5]), "=f"(r[6]), "=f"(r[7])
        : "l"(p));
}

__device__ __forceinline__ void ldg256(const float* p, float r[8]) {
    asm volatile("ld.global.nc.v8.f32 {%0,%1,%2,%3,%4,%5,%6,%7}, [%8];"
        : "=f"(r[0]), "=f"(r[1]), "=f"(r[2]), "=f"(r[3]),
          "=f"(r[4]), "=f"(r[5]), "=f"(r[6]), "=f"(r[7])
        : "l"(p));
}

__device__ __forceinline__ void stg256_ef(float* p, const float r[8]) {
    asm volatile("st.global.L2::evict_first.v8.f32 [%0], {%1,%2,%3,%4,%5,%6,%7,%8};"
        :: "l"(p),
           "f"(r[0]), "f"(r[1]), "f"(r[2]), "f"(r[3]),
           "f"(r[4]), "f"(r[5]), "f"(r[6]), "f"(r[7])
        : "memory");
}

__global__ __launch_bounds__(256, 2) void rope_kernel(
    const float* __restrict__ in,
    const float* __restrict__ sin_c,
    const float* __restrict__ cos_c,
    const int*   __restrict__ cu,
    float*       __restrict__ out)
{
    const int warp = threadIdx.x >> 5;
    const int lane = threadIdx.x & 31;
    const int t    = blockIdx.x * 8 + warp;   // one token per warp
    const int il   = lane & 15;               // lane within 16-lane head span

    const float* inb  = in  + (size_t)t * (N_HEAD * 128) + 8 * lane;
    float*       outb = out + (size_t)t * (N_HEAD * 128) + 8 * lane;

    // --- Prime the stream pipeline FIRST (independent of the search). ---
    // Chunk = 8 heads = 4 KB = 4x LDG.256.
    float v[4][8], w[4][8];
#pragma unroll
    for (int j = 0; j < 4; j++) ldg256_ef(inb + j * 256, v[j]);

    // --- One-shot ballot segment search (resolves under in-flight reads).
    const int c_l = (lane <= 16) ? __ldg(cu + lane) : 0x7fffffff;
    const unsigned m = __ballot_sync(0xffffffffu, c_l <= t);
    const int lo = 31 - __clz(m);
    const int off = t - __shfl_sync(0xffffffffu, c_l, lo);

    // sin/cos for this lane's 8 rope dims (reused tables: default policy).
    float s8[8], c8[8];
#pragma unroll
    for (int k = 0; k < 8; k++) { s8[k] = 0.f; c8[k] = 0.f; }
    if (il < 8) {
        ldg256(sin_c + (size_t)off * ROPE + 8 * il, s8);
        ldg256(cos_c + (size_t)off * ROPE + 8 * il, c8);
    }
    const float sg   = (il < 4) ? -1.0f : 1.0f;
    const bool  rope = (il < 8);

    // 4 chunks of 8 heads. 2-stage pipeline with 4 KB stages:
    // load chunk c+1 (4x LDG burst), then compute+store chunk c (4x STG burst).
#pragma unroll
    for (int c = 0; c < 4; c++) {
        if (c < 3) {
#pragma unroll
            for (int j = 0; j < 4; j++)
                ldg256_ef(inb + 1024 * (c + 1) + j * 256, w[j]);
        }

#pragma unroll
        for (int j = 0; j < 4; j++) {
            float r[8];
#pragma unroll
            for (int k = 0; k < 8; k++) {
                const float q = __shfl_xor_sync(0xffffffffu, v[j][k], 4);
                r[k] = rope ? fmaf(sg * q, s8[k], v[j][k] * c8[k]) : v[j][k];
            }
            stg256_ef(outb + 1024 * c + j * 256, r);
        }

#pragma unroll
        for (int j = 0; j < 4; j++)
#pragma unroll
            for (int k = 0; k < 8; k++)
                v[j][k] = w[j][k];
    }
}

extern "C" void kernel_launch(void* const* d_in, const int* in_sizes, int n_in,
                              void* d_out, int out_size)
{
    const float* in    = (const float*)d_in[0];
    const float* sin_c = (const float*)d_in[1];
    const float* cos_c = (const float*)d_in[2];
    const int*   cu    = (const int*)  d_in[3];
    float*       out   = (float*)d_out;

    const int blocks = N_TOK / 8;   // 4096 blocks, 8 warps each
    rope_kernel<<<blocks, 256>>>(in, sin_c, cos_c, cu, out);
}